// round 4
// baseline (speedup 1.0000x reference)
#include <cuda_runtime.h>
#include <cuda_bf16.h>
#include <cstdint>

#define HIDDEN 2048
#define SEQ    2048
#define BATCH  2
#define NHEADS 16
#define HDIM   128
#define MROWS  (BATCH * SEQ)   // 4096

typedef unsigned long long ull;

// ---------- f32x2 packed-math helpers ----------
__device__ __forceinline__ ull fpack2(float lo, float hi) {
    ull r; asm("mov.b64 %0, {%1,%2};" : "=l"(r) : "f"(lo), "f"(hi)); return r;
}
__device__ __forceinline__ ull fdup2(float v) { return fpack2(v, v); }
__device__ __forceinline__ float2 funpack2(ull v) {
    float2 r; asm("mov.b64 {%0,%1}, %2;" : "=f"(r.x), "=f"(r.y) : "l"(v)); return r;
}
__device__ __forceinline__ ull ffma2(ull a, ull b, ull c) {
    ull d; asm("fma.rn.f32x2 %0, %1, %2, %3;" : "=l"(d) : "l"(a), "l"(b), "l"(c)); return d;
}
__device__ __forceinline__ ull fmul2_(ull a, ull b) {
    ull d; asm("mul.rn.f32x2 %0, %1, %2;" : "=l"(d) : "l"(a), "l"(b)); return d;
}

// ---------- scratch ----------
__device__ float g_Q[MROWS * HIDDEN];
__device__ float g_K[MROWS * HIDDEN];
__device__ float g_V[MROWS * HIDDEN];
__device__ __nv_bfloat16 g_xh[MROWS * HIDDEN], g_xl[MROWS * HIDDEN];
__device__ __nv_bfloat16 g_oh[MROWS * HIDDEN], g_ol[MROWS * HIDDEN];
__device__ __nv_bfloat16 g_wqh[HIDDEN * HIDDEN], g_wql[HIDDEN * HIDDEN];
__device__ __nv_bfloat16 g_wkh[HIDDEN * HIDDEN], g_wkl[HIDDEN * HIDDEN];
__device__ __nv_bfloat16 g_wvh[HIDDEN * HIDDEN], g_wvl[HIDDEN * HIDDEN];
__device__ __nv_bfloat16 g_woh[HIDDEN * HIDDEN], g_wol[HIDDEN * HIDDEN];

// ---------- PTX wrappers (sm_80-era, valid on compute_103) ----------
__device__ __forceinline__ uint32_t smem_u32(const void* p) {
    uint32_t a;
    asm("{ .reg .u64 t; cvta.to.shared.u64 t, %1; cvt.u32.u64 %0, t; }" : "=r"(a) : "l"(p));
    return a;
}
__device__ __forceinline__ void cp16(uint32_t sdst, const void* gsrc) {
    asm volatile("cp.async.cg.shared.global [%0], [%1], 16;" :: "r"(sdst), "l"(gsrc) : "memory");
}
#define CP_COMMIT() asm volatile("cp.async.commit_group;" ::: "memory")
#define CP_WAITG2() asm volatile("cp.async.wait_group 2;" ::: "memory")

__device__ __forceinline__ void ldsm_x4(uint32_t (&r)[4], uint32_t addr) {
    asm volatile("ldmatrix.sync.aligned.m8n8.x4.shared.b16 {%0,%1,%2,%3}, [%4];"
                 : "=r"(r[0]), "=r"(r[1]), "=r"(r[2]), "=r"(r[3]) : "r"(addr));
}
__device__ __forceinline__ void mma16816(float (&d)[4], const uint32_t (&a)[4],
                                         uint32_t b0, uint32_t b1) {
    asm volatile(
        "mma.sync.aligned.m16n8k16.row.col.f32.bf16.bf16.f32 "
        "{%0,%1,%2,%3}, {%4,%5,%6,%7}, {%8,%9}, {%0,%1,%2,%3};"
        : "+f"(d[0]), "+f"(d[1]), "+f"(d[2]), "+f"(d[3])
        : "r"(a[0]), "r"(a[1]), "r"(a[2]), "r"(a[3]), "r"(b0), "r"(b1));
}

// ---------- fused fp32 -> bf16 hi/lo split for all 5 inputs ----------
// blocks: x [0,8192), wq [8192,12288), wk [12288,16384), wv [16384,20480), wo [20480,24576)
__global__ __launch_bounds__(256)
void cvt_all(const float4* __restrict__ x,  const float4* __restrict__ wq,
             const float4* __restrict__ wk, const float4* __restrict__ wv,
             const float4* __restrict__ wo,
             __nv_bfloat162* xh,  __nv_bfloat162* xl,
             __nv_bfloat162* wqh, __nv_bfloat162* wql,
             __nv_bfloat162* wkh, __nv_bfloat162* wkl,
             __nv_bfloat162* wvh, __nv_bfloat162* wvl,
             __nv_bfloat162* woh, __nv_bfloat162* wol)
{
    int bid = blockIdx.x;
    const float4* src; __nv_bfloat162 *ph, *pl; int base;
    if      (bid <  8192) { src = x;  ph = xh;  pl = xl;  base = bid; }
    else if (bid < 12288) { src = wq; ph = wqh; pl = wql; base = bid - 8192; }
    else if (bid < 16384) { src = wk; ph = wkh; pl = wkl; base = bid - 12288; }
    else if (bid < 20480) { src = wv; ph = wvh; pl = wvl; base = bid - 16384; }
    else                  { src = wo; ph = woh; pl = wol; base = bid - 20480; }
    size_t i = (size_t)base * 256 + threadIdx.x;
    float4 v = src[i];
    __nv_bfloat16 hx = __float2bfloat16(v.x);
    __nv_bfloat16 hy = __float2bfloat16(v.y);
    __nv_bfloat16 hz = __float2bfloat16(v.z);
    __nv_bfloat16 hw = __float2bfloat16(v.w);
    ph[2 * i]     = __halves2bfloat162(hx, hy);
    ph[2 * i + 1] = __halves2bfloat162(hz, hw);
    pl[2 * i]     = __halves2bfloat162(__float2bfloat16(v.x - __bfloat162float(hx)),
                                       __float2bfloat16(v.y - __bfloat162float(hy)));
    pl[2 * i + 1] = __halves2bfloat162(__float2bfloat16(v.z - __bfloat162float(hz)),
                                       __float2bfloat16(v.w - __bfloat162float(hw)));
}

// =====================================================================
// HMMA GEMM: C[M,N] = (Ah+Al)[M,K] @ (Bh+Bl)[N,K]^T, fp32 accum in regs.
// 128x128 CTA tile, 8 warps (4m x 2n), warp tile 32x64, BK=32.
// 80-byte padded smem rows (conflict-free, no XOR swizzle).
// 4-stage cp.async pipeline, prefetch distance 3, wait_group 2.
// 3 product passes (hh | lh | hl) -> accumulator dep distance 16.
// =====================================================================
#define BK       32
#define NKCH     (HIDDEN / BK)          // 64
#define ROWB     80
#define TILE_B   (128 * ROWB)           // 10240
#define STAGE_B  (4 * TILE_B)           // 40960: Ah Al Bh Bl
#define NSTAGE   4
#define GEMM_SMEM (NSTAGE * STAGE_B)    // 163840

__global__ __launch_bounds__(256, 1)
void gemm_mma(const __nv_bfloat16* __restrict__ Ah, const __nv_bfloat16* __restrict__ Al,
              const __nv_bfloat16* __restrict__ Bh, const __nv_bfloat16* __restrict__ Bl,
              float* __restrict__ C, int M, int N, int K)
{
    extern __shared__ __align__(128) char smem[];
    const uint32_t sbase = smem_u32(smem);
    const int tid  = threadIdx.x;
    const int wid  = tid >> 5;
    const int lane = tid & 31;
    const int wm   = wid & 3;
    const int wn   = wid >> 2;
    const size_t brow = (size_t)blockIdx.y * 128;
    const size_t bcol = (size_t)blockIdx.x * 128;

    // cp.async slots: row = tid>>1 (0..127), 2 segs of 16B each
    const int row  = tid >> 1;
    const int segq = (tid & 1) * 2;
    const uint32_t soff0 = (uint32_t)(row * ROWB + segq * 16);
    const uint32_t soff1 = soff0 + 16;

    const size_t Kb = (size_t)K * 2;
    const char* pAh = (const char*)Ah + (brow + row) * Kb + segq * 16;
    const char* pAl = (const char*)Al + (brow + row) * Kb + segq * 16;
    const char* pBh = (const char*)Bh + (bcol + row) * Kb + segq * 16;
    const char* pBl = (const char*)Bl + (bcol + row) * Kb + segq * 16;

#define LOAD_CHUNK(c, s) do {                                    \
        uint32_t sb_ = sbase + (uint32_t)(s) * STAGE_B;          \
        size_t g_ = (size_t)(c) * 64;                            \
        cp16(sb_ + 0 * TILE_B + soff0, pAh + g_);                \
        cp16(sb_ + 0 * TILE_B + soff1, pAh + g_ + 16);           \
        cp16(sb_ + 1 * TILE_B + soff0, pAl + g_);                \
        cp16(sb_ + 1 * TILE_B + soff1, pAl + g_ + 16);           \
        cp16(sb_ + 2 * TILE_B + soff0, pBh + g_);                \
        cp16(sb_ + 2 * TILE_B + soff1, pBh + g_ + 16);           \
        cp16(sb_ + 3 * TILE_B + soff0, pBl + g_);                \
        cp16(sb_ + 3 * TILE_B + soff1, pBl + g_ + 16);           \
    } while (0)

    // fragment addressing (80B rows, no swizzle)
    const int rA   = wm * 32 + (lane & 15);
    const int aSeg = lane >> 4;
    const int rB   = wn * 64 + ((lane >> 4) << 3) + (lane & 7);
    const int bSeg = (lane >> 3) & 1;

    float acc[2][8][4];
#pragma unroll
    for (int mt = 0; mt < 2; ++mt)
#pragma unroll
        for (int nt = 0; nt < 8; ++nt)
#pragma unroll
            for (int q = 0; q < 4; ++q) acc[mt][nt][q] = 0.f;

    LOAD_CHUNK(0, 0); CP_COMMIT();
    LOAD_CHUNK(1, 1); CP_COMMIT();
    LOAD_CHUNK(2, 2); CP_COMMIT();

    for (int c = 0; c < NKCH; ++c) {
        CP_WAITG2();          // chunk c arrived
        __syncthreads();      // all threads see it; all done with chunk c-1

        if (c + 3 < NKCH) LOAD_CHUNK(c + 3, (c + 3) & 3);
        CP_COMMIT();

        const uint32_t sb = sbase + (uint32_t)(c & 3) * STAGE_B;

#pragma unroll
        for (int k16 = 0; k16 < 2; ++k16) {
            uint32_t ah[2][4], al[2][4];
#pragma unroll
            for (int mt = 0; mt < 2; ++mt) {
                uint32_t byteoff = (uint32_t)((rA + mt * 16) * ROWB + (2 * k16 + aSeg) * 16);
                ldsm_x4(ah[mt], sb + 0 * TILE_B + byteoff);
                ldsm_x4(al[mt], sb + 1 * TILE_B + byteoff);
            }
            uint32_t bh[4][4], bl[4][4];
#pragma unroll
            for (int np = 0; np < 4; ++np) {
                uint32_t byteoff = (uint32_t)((rB + np * 16) * ROWB + (2 * k16 + bSeg) * 16);
                ldsm_x4(bh[np], sb + 2 * TILE_B + byteoff);
                ldsm_x4(bl[np], sb + 3 * TILE_B + byteoff);
            }
            // pass 1: Ah * Bh  (16 independent MMAs)
#pragma unroll
            for (int np = 0; np < 4; ++np)
#pragma unroll
                for (int mt = 0; mt < 2; ++mt) {
                    mma16816(acc[mt][2 * np + 0], ah[mt], bh[np][0], bh[np][1]);
                    mma16816(acc[mt][2 * np + 1], ah[mt], bh[np][2], bh[np][3]);
                }
            // pass 2: Al * Bh
#pragma unroll
            for (int np = 0; np < 4; ++np)
#pragma unroll
                for (int mt = 0; mt < 2; ++mt) {
                    mma16816(acc[mt][2 * np + 0], al[mt], bh[np][0], bh[np][1]);
                    mma16816(acc[mt][2 * np + 1], al[mt], bh[np][2], bh[np][3]);
                }
            // pass 3: Ah * Bl
#pragma unroll
            for (int np = 0; np < 4; ++np)
#pragma unroll
                for (int mt = 0; mt < 2; ++mt) {
                    mma16816(acc[mt][2 * np + 0], ah[mt], bl[np][0], bl[np][1]);
                    mma16816(acc[mt][2 * np + 1], ah[mt], bl[np][2], bl[np][3]);
                }
        }
    }

    // epilogue: direct fp32 stores
#pragma unroll
    for (int mt = 0; mt < 2; ++mt) {
        size_t r0 = brow + wm * 32 + mt * 16 + (lane >> 2);
#pragma unroll
        for (int nt = 0; nt < 8; ++nt) {
            size_t col = bcol + wn * 64 + nt * 8 + 2 * (lane & 3);
            *(float2*)&C[r0 * (size_t)N + col]       = make_float2(acc[mt][nt][0], acc[mt][nt][1]);
            *(float2*)&C[(r0 + 8) * (size_t)N + col] = make_float2(acc[mt][nt][2], acc[mt][nt][3]);
        }
    }
}

// =====================================================================
// Flash attention (non-causal), fp32 f32x2 core; writes O as bf16 hi/lo.
// =====================================================================
#define ATTN_SMEM_FLOATS (8192 + 8320 + 8448 + 5120)
#define ATTN_SMEM_BYTES  (ATTN_SMEM_FLOATS * 4)

__global__ __launch_bounds__(256, 1)
void attn_kernel(const float* __restrict__ Q, const float* __restrict__ K,
                 const float* __restrict__ V,
                 __nv_bfloat16* __restrict__ Oh, __nv_bfloat16* __restrict__ Ol)
{
    extern __shared__ __align__(16) float sm[];
    float* Qs = sm;                 // [64][128]
    float* Kt = sm + 8192;          // [64][130]
    float* Vt = sm + 16512;         // [128][66]
    float* Ps = sm + 24960;         // [64][80]

    const int tid = threadIdx.x;
    const int tx  = tid & 15;
    const int ty  = tid >> 4;
    const int b   = blockIdx.x >> 4;
    const int h   = blockIdx.x & 15;
    const int qt  = blockIdx.y;

    const float scale = 0.08838834764831843f;
    const size_t base = ((size_t)b * SEQ) * HIDDEN + (size_t)h * HDIM;

#pragma unroll
    for (int it = 0; it < 8; ++it) {
        int idx = it * 256 + tid;
        int r   = idx >> 5;
        int c4  = (idx & 31) << 2;
        float4 v = *(const float4*)(Q + base + (size_t)(qt * 64 + r) * HIDDEN + c4);
        v.x *= scale; v.y *= scale; v.z *= scale; v.w *= scale;
        *(float4*)&Qs[r * 128 + c4] = v;
    }

    ull   O2[4][8];
    float m_i[4], l_i[4];
#pragma unroll
    for (int i = 0; i < 4; ++i) {
        m_i[i] = -3.402823466e38f;
        l_i[i] = 0.f;
#pragma unroll
        for (int j = 0; j < 8; ++j) O2[i][j] = 0ull;
    }

    for (int kt = 0; kt < SEQ / 64; ++kt) {
        __syncthreads();
        const float* Kg = K + base + (size_t)(kt * 64) * HIDDEN;
        const float* Vg = V + base + (size_t)(kt * 64) * HIDDEN;
#pragma unroll
        for (int it = 0; it < 16; ++it) {
            int idx = it * 256 + tid;
            int r   = idx >> 6;
            int c2  = idx & 63;
            float2 kv = *(const float2*)(Kg + (size_t)r * HIDDEN + c2 * 2);
            *(float2*)&Kt[r * 130 + c2 * 2] = kv;
            float2 vv = *(const float2*)(Vg + (size_t)r * HIDDEN + c2 * 2);
            Vt[(c2 * 2    ) * 66 + r] = vv.x;
            Vt[(c2 * 2 + 1) * 66 + r] = vv.y;
        }
        __syncthreads();

        ull s2[4][4];
#pragma unroll
        for (int i = 0; i < 4; ++i)
#pragma unroll
            for (int j = 0; j < 4; ++j) s2[i][j] = 0ull;

#pragma unroll 2
        for (int d2 = 0; d2 < 64; ++d2) {
            ull q2[4], k2[4];
#pragma unroll
            for (int i = 0; i < 4; ++i)
                q2[i] = *(const ull*)&Qs[(ty * 4 + i) * 128 + d2 * 2];
#pragma unroll
            for (int j = 0; j < 4; ++j)
                k2[j] = *(const ull*)&Kt[(tx + 16 * j) * 130 + d2 * 2];
#pragma unroll
            for (int i = 0; i < 4; ++i)
#pragma unroll
                for (int j = 0; j < 4; ++j)
                    s2[i][j] = ffma2(q2[i], k2[j], s2[i][j]);
        }

#pragma unroll
        for (int i = 0; i < 4; ++i) {
            float s[4];
            float rmax = -3.402823466e38f;
#pragma unroll
            for (int j = 0; j < 4; ++j) {
                float2 f = funpack2(s2[i][j]);
                s[j] = f.x + f.y;
                rmax = fmaxf(rmax, s[j]);
            }
#pragma unroll
            for (int off = 8; off; off >>= 1)
                rmax = fmaxf(rmax, __shfl_xor_sync(0xffffffffu, rmax, off));
            float mnew = fmaxf(m_i[i], rmax);
            float c = __expf(m_i[i] - mnew);
            m_i[i] = mnew;
            float rsum = 0.f;
#pragma unroll
            for (int j = 0; j < 4; ++j) {
                float p = __expf(s[j] - mnew);
                rsum += p;
                Ps[(ty * 4 + i) * 80 + tx + 16 * j] = p;
            }
#pragma unroll
            for (int off = 8; off; off >>= 1)
                rsum += __shfl_xor_sync(0xffffffffu, rsum, off);
            l_i[i] = l_i[i] * c + rsum;
            ull cd = fdup2(c);
#pragma unroll
            for (int j = 0; j < 8; ++j) O2[i][j] = fmul2_(O2[i][j], cd);
        }
        __syncthreads();

#pragma unroll 2
        for (int kk = 0; kk < 32; ++kk) {
            ull p2[4], v2[8];
#pragma unroll
            for (int i = 0; i < 4; ++i)
                p2[i] = *(const ull*)&Ps[(ty * 4 + i) * 80 + kk * 2];
#pragma unroll
            for (int j = 0; j < 8; ++j)
                v2[j] = *(const ull*)&Vt[(tx + 16 * j) * 66 + kk * 2];
#pragma unroll
            for (int i = 0; i < 4; ++i)
#pragma unroll
                for (int j = 0; j < 8; ++j)
                    O2[i][j] = ffma2(p2[i], v2[j], O2[i][j]);
        }
    }

    // epilogue: fold pairs, normalize, write bf16 hi/lo directly
#pragma unroll
    for (int i = 0; i < 4; ++i) {
        float inv = 1.0f / l_i[i];
        size_t rowo = base + (size_t)(qt * 64 + ty * 4 + i) * HIDDEN;
#pragma unroll
        for (int j = 0; j < 8; ++j) {
            float2 f = funpack2(O2[i][j]);
            float o = (f.x + f.y) * inv;
            __nv_bfloat16 hb = __float2bfloat16(o);
            Oh[rowo + tx + 16 * j] = hb;
            Ol[rowo + tx + 16 * j] = __float2bfloat16(o - __bfloat162float(hb));
        }
    }
}

// =====================================================================
extern "C" void kernel_launch(void* const* d_in, const int* in_sizes, int n_in,
                              void* d_out, int out_size)
{
    const float* x  = (const float*)d_in[0];
    const float* wq = (const float*)d_in[1];
    const float* wk = (const float*)d_in[2];
    const float* wv = (const float*)d_in[3];
    const float* wo = (const float*)d_in[4];
    float* out = (float*)d_out;

    float *Qp, *Kp, *Vp;
    cudaGetSymbolAddress((void**)&Qp, g_Q);
    cudaGetSymbolAddress((void**)&Kp, g_K);
    cudaGetSymbolAddress((void**)&Vp, g_V);
    __nv_bfloat16 *xh, *xl, *oh, *ol;
    __nv_bfloat16 *wqh, *wql, *wkh, *wkl, *wvh, *wvl, *woh, *wol;
    cudaGetSymbolAddress((void**)&xh, g_xh);  cudaGetSymbolAddress((void**)&xl, g_xl);
    cudaGetSymbolAddress((void**)&oh, g_oh);  cudaGetSymbolAddress((void**)&ol, g_ol);
    cudaGetSymbolAddress((void**)&wqh, g_wqh); cudaGetSymbolAddress((void**)&wql, g_wql);
    cudaGetSymbolAddress((void**)&wkh, g_wkh); cudaGetSymbolAddress((void**)&wkl, g_wkl);
    cudaGetSymbolAddress((void**)&wvh, g_wvh); cudaGetSymbolAddress((void**)&wvl, g_wvl);
    cudaGetSymbolAddress((void**)&woh, g_woh); cudaGetSymbolAddress((void**)&wol, g_wol);

    const int M = MROWS;   // 4096

    // 1 launch: all fp32->bf16 hi/lo conversions
    cvt_all<<<24576, 256>>>((const float4*)x, (const float4*)wq, (const float4*)wk,
                            (const float4*)wv, (const float4*)wo,
                            (__nv_bfloat162*)xh,  (__nv_bfloat162*)xl,
                            (__nv_bfloat162*)wqh, (__nv_bfloat162*)wql,
                            (__nv_bfloat162*)wkh, (__nv_bfloat162*)wkl,
                            (__nv_bfloat162*)wvh, (__nv_bfloat162*)wvl,
                            (__nv_bfloat162*)woh, (__nv_bfloat162*)wol);

    cudaFuncSetAttribute(gemm_mma, cudaFuncAttributeMaxDynamicSharedMemorySize, GEMM_SMEM);
    dim3 ggrid(HIDDEN / 128, M / 128);   // (16, 32)
    gemm_mma<<<ggrid, 256, GEMM_SMEM>>>(xh, xl, wqh, wql, Qp, M, HIDDEN, HIDDEN);
    gemm_mma<<<ggrid, 256, GEMM_SMEM>>>(xh, xl, wkh, wkl, Kp, M, HIDDEN, HIDDEN);
    gemm_mma<<<ggrid, 256, GEMM_SMEM>>>(xh, xl, wvh, wvl, Vp, M, HIDDEN, HIDDEN);

    cudaFuncSetAttribute(attn_kernel, cudaFuncAttributeMaxDynamicSharedMemorySize,
                         ATTN_SMEM_BYTES);
    attn_kernel<<<dim3(BATCH * NHEADS, SEQ / 64), 256, ATTN_SMEM_BYTES>>>(Qp, Kp, Vp, oh, ol);

    gemm_mma<<<ggrid, 256, GEMM_SMEM>>>(oh, ol, woh, wol, out, M, HIDDEN, HIDDEN);
}